// round 13
// baseline (speedup 1.0000x reference)
#include <cuda_runtime.h>
#include <cuda_fp16.h>
#include <math.h>
#include <stdint.h>

#define N_NODES 10000
#define N_EDGES 320000
#define IN_F    256
#define HD      256
#define NH      4
#define D1      64
#define OUTF    47
#define OUTP    48
#define NEG     0.2f

// ---------------- scratch: vector-typed so 16B alignment is guaranteed ------
__device__ uint4  g_feat1v[N_NODES * 32];   // 256 fp16 ch = 32 uint4 per node
__device__ float4 g_h2v   [N_NODES * 64];   // 256 fp32  = 64 float4 per node
__device__ float4 g_el1v  [N_NODES];        // 4 heads
__device__ float4 g_er1v  [N_NODES];
__device__ float  g_feat2 [N_NODES * OUTP];
__device__ float  g_el2   [N_NODES];
__device__ float  g_er2   [N_NODES];

__device__ int   g_deg   [N_NODES];   // zero at launch entry (scan re-zeroes)
__device__ int   g_rowptr[N_NODES + 1];
__device__ int   g_cursor[N_NODES];   // zeroed by scan before scatter
__device__ int   g_esrc  [N_EDGES];

__device__ __forceinline__ float tf32r(float x) {
    uint32_t u;
    asm("cvt.rna.tf32.f32 %0, %1;" : "=r"(u) : "f"(x));
    return __uint_as_float(u);
}

// ---------------- CSR: count ----------------
__global__ void count_kernel(const int* __restrict__ dst, int E) {
    int e4 = (blockIdx.x * blockDim.x + threadIdx.x) * 4;
    if (e4 + 3 < E) {
        int4 d = *(const int4*)&dst[e4];
        atomicAdd(&g_deg[d.x], 1); atomicAdd(&g_deg[d.y], 1);
        atomicAdd(&g_deg[d.z], 1); atomicAdd(&g_deg[d.w], 1);
    } else {
        for (int e = e4; e < E; e++) atomicAdd(&g_deg[dst[e]], 1);
    }
}

// ---------------- CSR: scan (also resets g_deg & g_cursor for reuse) --------
__global__ void scan_kernel() {
    __shared__ int part[1024];
    const int PER = (N_NODES + 1023) / 1024;   // 10
    int t = threadIdx.x;
    int base = t * PER;
    int loc[PER];
    int sum = 0;
#pragma unroll
    for (int i = 0; i < PER; i++) {
        int idx = base + i;
        int v = (idx < N_NODES) ? g_deg[idx] : 0;
        sum += v;
        loc[i] = sum;
        if (idx < N_NODES) { g_deg[idx] = 0; g_cursor[idx] = 0; }
    }
    part[t] = sum;
    __syncthreads();
    for (int off = 1; off < 1024; off <<= 1) {
        int add = (t >= off) ? part[t - off] : 0;
        __syncthreads();
        part[t] += add;
        __syncthreads();
    }
    int offset = (t > 0) ? part[t - 1] : 0;
#pragma unroll
    for (int i = 0; i < PER; i++) {
        int idx = base + i;
        if (idx < N_NODES) g_rowptr[idx + 1] = offset + loc[i];
    }
    if (t == 0) g_rowptr[0] = 0;
}

// ---------------- FUSED: gemm1 (128x64, head/block) ∥ scatter (R11 config) --
__global__ void gemm1_scatter_kernel(const float* __restrict__ A,
                                     const float* __restrict__ B,
                                     const float* __restrict__ al,
                                     const float* __restrict__ ar,
                                     const int* __restrict__ src,
                                     const int* __restrict__ dst,
                                     int N, int E, int gx) {
    __shared__ float As[128][36];
    __shared__ float Bs[32][72];
    __shared__ float el_sh[128], er_sh[128];

    int b = blockIdx.x;
    int tid = threadIdx.x;

    if (b >= gx * NH) {
        // ---- scatter branch: 4 edges/thread ----
        int sb = b - gx * NH;
        int e4 = (sb * blockDim.x + tid) * 4;
        if (e4 + 3 < E) {
            int4 s = *(const int4*)&src[e4];
            int4 d = *(const int4*)&dst[e4];
            g_esrc[g_rowptr[d.x] + atomicAdd(&g_cursor[d.x], 1)] = s.x;
            g_esrc[g_rowptr[d.y] + atomicAdd(&g_cursor[d.y], 1)] = s.y;
            g_esrc[g_rowptr[d.z] + atomicAdd(&g_cursor[d.z], 1)] = s.z;
            g_esrc[g_rowptr[d.w] + atomicAdd(&g_cursor[d.w], 1)] = s.w;
        } else {
            for (int e = e4; e < E; e++) {
                int d = dst[e];
                g_esrc[g_rowptr[d] + atomicAdd(&g_cursor[d], 1)] = src[e];
            }
        }
        return;
    }

    // ---- GEMM1 branch ----
    int wid  = tid >> 5, lane = tid & 31;
    int g    = lane >> 2, tig = lane & 3;
    int warpM = wid >> 1, warpN = wid & 1;
    int h    = b / gx;
    int row0 = (b % gx) * 128, col0 = h * 64;

    __half2* f1h = reinterpret_cast<__half2*>(g_feat1v);
    float*   el1 = reinterpret_cast<float*>(g_el1v);
    float*   er1 = reinterpret_cast<float*>(g_er1v);

    if (tid < 128) { el_sh[tid] = 0.f; er_sh[tid] = 0.f; }

    float c[2][4][4];
#pragma unroll
    for (int mf = 0; mf < 2; mf++)
#pragma unroll
        for (int nf = 0; nf < 4; nf++)
#pragma unroll
            for (int j = 0; j < 4; j++) c[mf][nf][j] = 0.f;

    for (int kk = 0; kk < IN_F; kk += 32) {
#pragma unroll
        for (int i = 0; i < 4; i++) {
            int idx = tid + i * 256;
            int m = idx >> 3, kq = (idx & 7) * 4;
            int r = row0 + m;
            float4 v = (r < N) ? *(const float4*)&A[r * IN_F + kk + kq]
                               : make_float4(0.f, 0.f, 0.f, 0.f);
            As[m][kq + 0] = tf32r(v.x); As[m][kq + 1] = tf32r(v.y);
            As[m][kq + 2] = tf32r(v.z); As[m][kq + 3] = tf32r(v.w);
        }
#pragma unroll
        for (int i = 0; i < 2; i++) {
            int idx = tid + i * 256;
            int k = idx >> 4, nq = (idx & 15) * 4;
            float4 v = *(const float4*)&B[(kk + k) * HD + col0 + nq];
            Bs[k][nq + 0] = tf32r(v.x); Bs[k][nq + 1] = tf32r(v.y);
            Bs[k][nq + 2] = tf32r(v.z); Bs[k][nq + 3] = tf32r(v.w);
        }
        __syncthreads();

#pragma unroll
        for (int ks = 0; ks < 32; ks += 8) {
            uint32_t af[2][4], bf[4][2];
#pragma unroll
            for (int mf = 0; mf < 2; mf++) {
                int mbase = warpM * 32 + mf * 16;
                af[mf][0] = __float_as_uint(As[mbase + g    ][ks + tig    ]);
                af[mf][1] = __float_as_uint(As[mbase + g + 8][ks + tig    ]);
                af[mf][2] = __float_as_uint(As[mbase + g    ][ks + tig + 4]);
                af[mf][3] = __float_as_uint(As[mbase + g + 8][ks + tig + 4]);
            }
#pragma unroll
            for (int nf = 0; nf < 4; nf++) {
                int nbase = warpN * 32 + nf * 8;
                bf[nf][0] = __float_as_uint(Bs[ks + tig    ][nbase + g]);
                bf[nf][1] = __float_as_uint(Bs[ks + tig + 4][nbase + g]);
            }
#pragma unroll
            for (int mf = 0; mf < 2; mf++)
#pragma unroll
                for (int nf = 0; nf < 4; nf++) {
                    asm volatile(
                        "mma.sync.aligned.m16n8k8.row.col.f32.tf32.tf32.f32 "
                        "{%0,%1,%2,%3}, {%4,%5,%6,%7}, {%8,%9}, {%0,%1,%2,%3};"
                        : "+f"(c[mf][nf][0]), "+f"(c[mf][nf][1]),
                          "+f"(c[mf][nf][2]), "+f"(c[mf][nf][3])
                        : "r"(af[mf][0]), "r"(af[mf][1]),
                          "r"(af[mf][2]), "r"(af[mf][3]),
                          "r"(bf[nf][0]), "r"(bf[nf][1]));
                }
        }
        __syncthreads();
    }

    float alv[4][2], arv[4][2];
#pragma unroll
    for (int nf = 0; nf < 4; nf++)
#pragma unroll
        for (int j = 0; j < 2; j++) {
            int col = warpN * 32 + nf * 8 + 2 * tig + j;
            alv[nf][j] = al[h * D1 + col];
            arv[nf][j] = ar[h * D1 + col];
        }

#pragma unroll
    for (int mf = 0; mf < 2; mf++) {
        int lr0 = warpM * 32 + mf * 16 + g;
        int lr1 = lr0 + 8;
        int r0g = row0 + lr0, r1g = row0 + lr1;
        float el0 = 0.f, er0 = 0.f, el1v = 0.f, er1v = 0.f;
#pragma unroll
        for (int nf = 0; nf < 4; nf++) {
            int colw = warpN * 32 + nf * 8 + 2 * tig;
            int cp = (col0 + colw) >> 1;
            if (r0g < N)
                f1h[r0g * (HD/2) + cp] = __floats2half2_rn(c[mf][nf][0], c[mf][nf][1]);
            if (r1g < N)
                f1h[r1g * (HD/2) + cp] = __floats2half2_rn(c[mf][nf][2], c[mf][nf][3]);
            el0 += c[mf][nf][0] * alv[nf][0] + c[mf][nf][1] * alv[nf][1];
            er0 += c[mf][nf][0] * arv[nf][0] + c[mf][nf][1] * arv[nf][1];
            el1v += c[mf][nf][2] * alv[nf][0] + c[mf][nf][3] * alv[nf][1];
            er1v += c[mf][nf][2] * arv[nf][0] + c[mf][nf][3] * arv[nf][1];
        }
#pragma unroll
        for (int o = 1; o < 4; o <<= 1) {
            el0  += __shfl_xor_sync(0xffffffffu, el0,  o, 4);
            er0  += __shfl_xor_sync(0xffffffffu, er0,  o, 4);
            el1v += __shfl_xor_sync(0xffffffffu, el1v, o, 4);
            er1v += __shfl_xor_sync(0xffffffffu, er1v, o, 4);
        }
        if (tig == 0) {
            atomicAdd(&el_sh[lr0], el0);  atomicAdd(&er_sh[lr0], er0);
            atomicAdd(&el_sh[lr1], el1v); atomicAdd(&er_sh[lr1], er1v);
        }
    }
    __syncthreads();
    if (tid < 128) {
        int r = row0 + tid;
        if (r < N) {
            el1[r * NH + h] = el_sh[tid];
            er1[r * NH + h] = er_sh[tid];
        }
    }
}

// ---------------- layer1: softmax + agg + elu; HFMA2 inner loop -------------
__global__ void sfm_agg1_kernel(int N) {
    __shared__ int     s_sh[8][32];
    __shared__ __half2 w_sh[8][NH][32];   // (w,w) per head per edge

    int tid = threadIdx.x;
    int wid = tid >> 5, lane = tid & 31;
    int n = blockIdx.x * 8 + wid;
    if (n >= N) return;

    int r0 = g_rowptr[n];
    int deg = g_rowptr[n + 1] - r0;
    float4 ern4 = g_er1v[n];

    float mx[NH] = {-INFINITY, -INFINITY, -INFINITY, -INFINITY};
    for (int i = lane; i < deg; i += 32) {
        int s = g_esrc[r0 + i];
        float4 el4 = g_el1v[s];
        float x0 = el4.x + ern4.x; x0 = (x0 > 0.f) ? x0 : NEG * x0;
        float x1 = el4.y + ern4.y; x1 = (x1 > 0.f) ? x1 : NEG * x1;
        float x2 = el4.z + ern4.z; x2 = (x2 > 0.f) ? x2 : NEG * x2;
        float x3 = el4.w + ern4.w; x3 = (x3 > 0.f) ? x3 : NEG * x3;
        mx[0] = fmaxf(mx[0], x0); mx[1] = fmaxf(mx[1], x1);
        mx[2] = fmaxf(mx[2], x2); mx[3] = fmaxf(mx[3], x3);
    }
#pragma unroll
    for (int h = 0; h < NH; h++)
#pragma unroll
        for (int o = 16; o; o >>= 1)
            mx[h] = fmaxf(mx[h], __shfl_xor_sync(0xffffffffu, mx[h], o));

    float den[NH] = {0.f, 0.f, 0.f, 0.f};
    for (int i = lane; i < deg; i += 32) {
        int s = g_esrc[r0 + i];
        float4 el4 = g_el1v[s];
        float x0 = el4.x + ern4.x; x0 = (x0 > 0.f) ? x0 : NEG * x0;
        float x1 = el4.y + ern4.y; x1 = (x1 > 0.f) ? x1 : NEG * x1;
        float x2 = el4.z + ern4.z; x2 = (x2 > 0.f) ? x2 : NEG * x2;
        float x3 = el4.w + ern4.w; x3 = (x3 > 0.f) ? x3 : NEG * x3;
        den[0] += __expf(x0 - mx[0]); den[1] += __expf(x1 - mx[1]);
        den[2] += __expf(x2 - mx[2]); den[3] += __expf(x3 - mx[3]);
    }
#pragma unroll
    for (int h = 0; h < NH; h++)
#pragma unroll
        for (int o = 16; o; o >>= 1)
            den[h] += __shfl_xor_sync(0xffffffffu, den[h], o);

    float idw[NH];
#pragma unroll
    for (int h = 0; h < NH; h++) idw[h] = 1.f / fmaxf(den[h], 1e-9f);

    int hme = lane >> 3;
    float facc[8] = {};
    __half2 zero2 = __float2half2_rn(0.f);
    __half2 hacc0 = zero2, hacc1 = zero2, hacc2 = zero2, hacc3 = zero2;

    for (int i0 = 0; i0 < deg; i0 += 32) {
        int cnt = min(32, deg - i0);
        if (lane < cnt) {
            int s = g_esrc[r0 + i0 + lane];
            s_sh[wid][lane] = s;
            float4 el4 = g_el1v[s];
            float x0 = el4.x + ern4.x; x0 = (x0 > 0.f) ? x0 : NEG * x0;
            float x1 = el4.y + ern4.y; x1 = (x1 > 0.f) ? x1 : NEG * x1;
            float x2 = el4.z + ern4.z; x2 = (x2 > 0.f) ? x2 : NEG * x2;
            float x3 = el4.w + ern4.w; x3 = (x3 > 0.f) ? x3 : NEG * x3;
            w_sh[wid][0][lane] = __float2half2_rn(__expf(x0 - mx[0]) * idw[0]);
            w_sh[wid][1][lane] = __float2half2_rn(__expf(x1 - mx[1]) * idw[1]);
            w_sh[wid][2][lane] = __float2half2_rn(__expf(x2 - mx[2]) * idw[2]);
            w_sh[wid][3][lane] = __float2half2_rn(__expf(x3 - mx[3]) * idw[3]);
        }
        __syncwarp();
        for (int i = 0; i < cnt; i++) {
            int s = s_sh[wid][i];
            __half2 w2 = w_sh[wid][hme][i];
            uint4 raw = g_feat1v[s * 32 + lane];
            hacc0 = __hfma2(*reinterpret_cast<__half2*>(&raw.x), w2, hacc0);
            hacc1 = __hfma2(*reinterpret_cast<__half2*>(&raw.y), w2, hacc1);
            hacc2 = __hfma2(*reinterpret_cast<__half2*>(&raw.z), w2, hacc2);
            hacc3 = __hfma2(*reinterpret_cast<__half2*>(&raw.w), w2, hacc3);
            if ((i & 7) == 7) {   // flush partials to fp32 every 8 edges
                float2 t;
                t = __half22float2(hacc0); facc[0] += t.x; facc[1] += t.y;
                t = __half22float2(hacc1); facc[2] += t.x; facc[3] += t.y;
                t = __half22float2(hacc2); facc[4] += t.x; facc[5] += t.y;
                t = __half22float2(hacc3); facc[6] += t.x; facc[7] += t.y;
                hacc0 = zero2; hacc1 = zero2; hacc2 = zero2; hacc3 = zero2;
            }
        }
        __syncwarp();
    }
    {   // final flush (remainder)
        float2 t;
        t = __half22float2(hacc0); facc[0] += t.x; facc[1] += t.y;
        t = __half22float2(hacc1); facc[2] += t.x; facc[3] += t.y;
        t = __half22float2(hacc2); facc[4] += t.x; facc[5] += t.y;
        t = __half22float2(hacc3); facc[6] += t.x; facc[7] += t.y;
    }

    float o[8];
#pragma unroll
    for (int q = 0; q < 8; q++)
        o[q] = (facc[q] > 0.f) ? facc[q] : expm1f(facc[q]);
    g_h2v[n * 64 + lane * 2]     = make_float4(o[0], o[1], o[2], o[3]);
    g_h2v[n * 64 + lane * 2 + 1] = make_float4(o[4], o[5], o[6], o[7]);
}

// ---------------- layer2 GEMM (tf32 mma) + attention dots -------------------
__global__ void gemm2_attn_kernel(const float* __restrict__ W2,
                                  const float* __restrict__ al2,
                                  const float* __restrict__ ar2, int N) {
    __shared__ float As[128][36];
    __shared__ float Bs[32][72];
    __shared__ float el_sh[128], er_sh[128];

    int tid  = threadIdx.x;
    int wid  = tid >> 5, lane = tid & 31;
    int g    = lane >> 2, tig = lane & 3;
    int warpM = wid >> 1, warpN = wid & 1;
    int row0 = blockIdx.x * 128;

    if (tid < 128) { el_sh[tid] = 0.f; er_sh[tid] = 0.f; }

    float c[2][4][4];
#pragma unroll
    for (int mf = 0; mf < 2; mf++)
#pragma unroll
        for (int nf = 0; nf < 4; nf++)
#pragma unroll
            for (int j = 0; j < 4; j++) c[mf][nf][j] = 0.f;

    for (int kk = 0; kk < HD; kk += 32) {
#pragma unroll
        for (int i = 0; i < 4; i++) {
            int idx = tid + i * 256;
            int m = idx >> 3, kq = (idx & 7) * 4;
            int r = row0 + m;
            float4 v = (r < N) ? g_h2v[r * 64 + (kk + kq) / 4]
                               : make_float4(0.f, 0.f, 0.f, 0.f);
            As[m][kq + 0] = tf32r(v.x); As[m][kq + 1] = tf32r(v.y);
            As[m][kq + 2] = tf32r(v.z); As[m][kq + 3] = tf32r(v.w);
        }
#pragma unroll
        for (int i = 0; i < 8; i++) {
            int idx = tid + i * 256;
            int k = idx >> 6, nn = idx & 63;
            Bs[k][nn] = (nn < OUTF) ? tf32r(W2[(kk + k) * OUTF + nn]) : 0.f;
        }
        __syncthreads();

#pragma unroll
        for (int ks = 0; ks < 32; ks += 8) {
            uint32_t af[2][4], bf[4][2];
#pragma unroll
            for (int mf = 0; mf < 2; mf++) {
                int mbase = warpM * 32 + mf * 16;
                af[mf][0] = __float_as_uint(As[mbase + g    ][ks + tig    ]);
                af[mf][1] = __float_as_uint(As[mbase + g + 8][ks + tig    ]);
                af[mf][2] = __float_as_uint(As[mbase + g    ][ks + tig + 4]);
                af[mf][3] = __float_as_uint(As[mbase + g + 8][ks + tig + 4]);
            }
#pragma unroll
            for (int nf = 0; nf < 4; nf++) {
                int nbase = warpN * 32 + nf * 8;
                bf[nf][0] = __float_as_uint(Bs[ks + tig    ][nbase + g]);
                bf[nf][1] = __float_as_uint(Bs[ks + tig + 4][nbase + g]);
            }
#pragma unroll
            for (int mf = 0; mf < 2; mf++)
#pragma unroll
                for (int nf = 0; nf < 4; nf++) {
                    asm volatile(
                        "mma.sync.aligned.m16n8k8.row.col.f32.tf32.tf32.f32 "
                        "{%0,%1,%2,%3}, {%4,%5,%6,%7}, {%8,%9}, {%0,%1,%2,%3};"
                        : "+f"(c[mf][nf][0]), "+f"(c[mf][nf][1]),
                          "+f"(c[mf][nf][2]), "+f"(c[mf][nf][3])
                        : "r"(af[mf][0]), "r"(af[mf][1]),
                          "r"(af[mf][2]), "r"(af[mf][3]),
                          "r"(bf[nf][0]), "r"(bf[nf][1]));
                }
        }
        __syncthreads();
    }

    float alv[4][2], arv[4][2];
#pragma unroll
    for (int nf = 0; nf < 4; nf++)
#pragma unroll
        for (int j = 0; j < 2; j++) {
            int col = warpN * 32 + nf * 8 + 2 * tig + j;
            alv[nf][j] = (col < OUTF) ? al2[col] : 0.f;
            arv[nf][j] = (col < OUTF) ? ar2[col] : 0.f;
        }

#pragma unroll
    for (int mf = 0; mf < 2; mf++) {
        int lr0 = warpM * 32 + mf * 16 + g;
        int lr1 = lr0 + 8;
        int r0g = row0 + lr0, r1g = row0 + lr1;
        float el0 = 0.f, er0 = 0.f, el1v = 0.f, er1v = 0.f;
#pragma unroll
        for (int nf = 0; nf < 4; nf++) {
            int colw = warpN * 32 + nf * 8 + 2 * tig;
#pragma unroll
            for (int j = 0; j < 2; j++) {
                int col = colw + j;
                if (col < OUTF) {
                    if (r0g < N) g_feat2[r0g * OUTP + col] = c[mf][nf][j];
                    if (r1g < N) g_feat2[r1g * OUTP + col] = c[mf][nf][2 + j];
                }
            }
            el0 += c[mf][nf][0] * alv[nf][0] + c[mf][nf][1] * alv[nf][1];
            er0 += c[mf][nf][0] * arv[nf][0] + c[mf][nf][1] * arv[nf][1];
            el1v += c[mf][nf][2] * alv[nf][0] + c[mf][nf][3] * alv[nf][1];
            er1v += c[mf][nf][2] * arv[nf][0] + c[mf][nf][3] * arv[nf][1];
        }
#pragma unroll
        for (int o = 1; o < 4; o <<= 1) {
            el0  += __shfl_xor_sync(0xffffffffu, el0,  o, 4);
            er0  += __shfl_xor_sync(0xffffffffu, er0,  o, 4);
            el1v += __shfl_xor_sync(0xffffffffu, el1v, o, 4);
            er1v += __shfl_xor_sync(0xffffffffu, er1v, o, 4);
        }
        if (tig == 0) {
            atomicAdd(&el_sh[lr0], el0);  atomicAdd(&er_sh[lr0], er0);
            atomicAdd(&el_sh[lr1], el1v); atomicAdd(&er_sh[lr1], er1v);
        }
    }
    __syncthreads();
    if (tid < 128) {
        int r = row0 + tid;
        if (r < N) {
            g_el2[r] = el_sh[tid];
            g_er2[r] = er_sh[tid];
        }
    }
}

// ---------------- layer2: softmax + agg + log_softmax (warp per node) -------
__global__ void agg2_ls_kernel(float* __restrict__ out, int N) {
    int warp = threadIdx.x >> 5;
    int lane = threadIdx.x & 31;
    int n = blockIdx.x * 4 + warp;
    if (n >= N) return;
    int r0 = g_rowptr[n];
    int deg = g_rowptr[n + 1] - r0;
    float ern = g_er2[n];

    float mx = -INFINITY;
    for (int i = lane; i < deg; i += 32) {
        int s = g_esrc[r0 + i];
        float x = g_el2[s] + ern;
        x = (x > 0.f) ? x : NEG * x;
        mx = fmaxf(mx, x);
    }
#pragma unroll
    for (int o = 16; o; o >>= 1)
        mx = fmaxf(mx, __shfl_xor_sync(0xffffffffu, mx, o));

    float den = 0.f;
    for (int i = lane; i < deg; i += 32) {
        int s = g_esrc[r0 + i];
        float x = g_el2[s] + ern;
        x = (x > 0.f) ? x : NEG * x;
        den += __expf(x - mx);
    }
#pragma unroll
    for (int o = 16; o; o >>= 1)
        den += __shfl_xor_sync(0xffffffffu, den, o);
    den = fmaxf(den, 1e-9f);

    bool hi = (lane + 32) < OUTF;
    float a0 = 0.f, a1 = 0.f;
    for (int i = 0; i < deg; i++) {
        int s = g_esrc[r0 + i];
        float x = g_el2[s] + ern;
        x = (x > 0.f) ? x : NEG * x;
        float w = __expf(x - mx);
        a0 += w * g_feat2[s * OUTP + lane];
        if (hi) a1 += w * g_feat2[s * OUTP + lane + 32];
    }
    a0 /= den;
    a1 /= den;

    float v0 = a0;
    float v1 = hi ? a1 : -INFINITY;
    float m2 = fmaxf(v0, v1);
#pragma unroll
    for (int o = 16; o; o >>= 1)
        m2 = fmaxf(m2, __shfl_xor_sync(0xffffffffu, m2, o));
    float s_ = expf(v0 - m2) + (hi ? expf(v1 - m2) : 0.f);
#pragma unroll
    for (int o = 16; o; o >>= 1)
        s_ += __shfl_xor_sync(0xffffffffu, s_, o);
    float ls = logf(s_) + m2;
    out[n * OUTF + lane] = v0 - ls;
    if (hi) out[n * OUTF + lane + 32] = v1 - ls;
}

// ---------------- launch ----------------
extern "C" void kernel_launch(void* const* d_in, const int* in_sizes, int n_in,
                              void* d_out, int out_size) {
    const float* features = (const float*)d_in[0];
    const int*   src      = (const int*)d_in[1];
    const int*   dst      = (const int*)d_in[2];
    const float* W1       = (const float*)d_in[3];
    const float* al1      = (const float*)d_in[4];
    const float* ar1      = (const float*)d_in[5];
    const float* W2       = (const float*)d_in[6];
    const float* al2      = (const float*)d_in[7];
    const float* ar2      = (const float*)d_in[8];
    float* out = (float*)d_out;

    int N = in_sizes[0] / IN_F;   // 10000
    int E = in_sizes[1];          // 320000
    if (N > N_NODES) N = N_NODES;
    if (E > N_EDGES) E = N_EDGES;

    int e4blocks = (E / 4 + 255) / 256 + 1;
    count_kernel<<<e4blocks, 256>>>(dst, E);
    scan_kernel<<<1, 1024>>>();

    int gx = (N + 127) / 128;
    gemm1_scatter_kernel<<<gx * NH + e4blocks, 256>>>(
        features, W1, al1, ar1, src, dst, N, E, gx);

    sfm_agg1_kernel<<<(N + 7) / 8, 256>>>(N);
    gemm2_attn_kernel<<<(N + 127) / 128, 256>>>(W2, al2, ar2, N);
    agg2_ls_kernel<<<(N + 3) / 4, 128>>>(out, N);
}

// round 14
// speedup vs baseline: 1.4391x; 1.4391x over previous
#include <cuda_runtime.h>
#include <cuda_fp16.h>
#include <math.h>
#include <stdint.h>

#define N_NODES 10000
#define N_EDGES 320000
#define IN_F    256
#define HD      256
#define NH      4
#define D1      64
#define OUTF    47
#define OUTP    48
#define NEG     0.2f

// ---------------- scratch: vector-typed so 16B alignment is guaranteed ------
__device__ uint4  g_feat1v[N_NODES * 32];   // 256 fp16 ch = 32 uint4 per node
__device__ float4 g_h2v   [N_NODES * 64];   // 256 fp32  = 64 float4 per node
__device__ float4 g_el1v  [N_NODES];        // 4 heads
__device__ float4 g_er1v  [N_NODES];
__device__ float  g_feat2 [N_NODES * OUTP];
__device__ float  g_el2   [N_NODES];
__device__ float  g_er2   [N_NODES];

__device__ int   g_deg   [N_NODES];   // zero at launch entry (scan re-zeroes)
__device__ int   g_rowptr[N_NODES + 1];
__device__ int   g_cursor[N_NODES];   // zeroed by scan before scatter
__device__ int   g_esrc  [N_EDGES];

__device__ __forceinline__ float tf32r(float x) {
    uint32_t u;
    asm("cvt.rna.tf32.f32 %0, %1;" : "=r"(u) : "f"(x));
    return __uint_as_float(u);
}

// ---------------- CSR: count ----------------
__global__ void count_kernel(const int* __restrict__ dst, int E) {
    int e4 = (blockIdx.x * blockDim.x + threadIdx.x) * 4;
    if (e4 + 3 < E) {
        int4 d = *(const int4*)&dst[e4];
        atomicAdd(&g_deg[d.x], 1); atomicAdd(&g_deg[d.y], 1);
        atomicAdd(&g_deg[d.z], 1); atomicAdd(&g_deg[d.w], 1);
    } else {
        for (int e = e4; e < E; e++) atomicAdd(&g_deg[dst[e]], 1);
    }
}

// ---------------- CSR: scan (also resets g_deg & g_cursor for reuse) --------
__global__ void scan_kernel() {
    __shared__ int part[1024];
    const int PER = (N_NODES + 1023) / 1024;   // 10
    int t = threadIdx.x;
    int base = t * PER;
    int loc[PER];
    int sum = 0;
#pragma unroll
    for (int i = 0; i < PER; i++) {
        int idx = base + i;
        int v = (idx < N_NODES) ? g_deg[idx] : 0;
        sum += v;
        loc[i] = sum;
        if (idx < N_NODES) { g_deg[idx] = 0; g_cursor[idx] = 0; }
    }
    part[t] = sum;
    __syncthreads();
    for (int off = 1; off < 1024; off <<= 1) {
        int add = (t >= off) ? part[t - off] : 0;
        __syncthreads();
        part[t] += add;
        __syncthreads();
    }
    int offset = (t > 0) ? part[t - 1] : 0;
#pragma unroll
    for (int i = 0; i < PER; i++) {
        int idx = base + i;
        if (idx < N_NODES) g_rowptr[idx + 1] = offset + loc[i];
    }
    if (t == 0) g_rowptr[0] = 0;
}

// ---------------- FUSED: gemm1 (128x64, head/block) ∥ scatter ----------------
__global__ void gemm1_scatter_kernel(const float* __restrict__ A,
                                     const float* __restrict__ B,
                                     const float* __restrict__ al,
                                     const float* __restrict__ ar,
                                     const int* __restrict__ src,
                                     const int* __restrict__ dst,
                                     int N, int E, int gx) {
    __shared__ float As[128][36];
    __shared__ float Bs[32][72];
    __shared__ float el_sh[128], er_sh[128];

    int b = blockIdx.x;
    int tid = threadIdx.x;

    if (b >= gx * NH) {
        // ---- scatter branch: 4 edges/thread ----
        int sb = b - gx * NH;
        int e4 = (sb * blockDim.x + tid) * 4;
        if (e4 + 3 < E) {
            int4 s = *(const int4*)&src[e4];
            int4 d = *(const int4*)&dst[e4];
            g_esrc[g_rowptr[d.x] + atomicAdd(&g_cursor[d.x], 1)] = s.x;
            g_esrc[g_rowptr[d.y] + atomicAdd(&g_cursor[d.y], 1)] = s.y;
            g_esrc[g_rowptr[d.z] + atomicAdd(&g_cursor[d.z], 1)] = s.z;
            g_esrc[g_rowptr[d.w] + atomicAdd(&g_cursor[d.w], 1)] = s.w;
        } else {
            for (int e = e4; e < E; e++) {
                int d = dst[e];
                g_esrc[g_rowptr[d] + atomicAdd(&g_cursor[d], 1)] = src[e];
            }
        }
        return;
    }

    // ---- GEMM1 branch ----
    int wid  = tid >> 5, lane = tid & 31;
    int g    = lane >> 2, tig = lane & 3;
    int warpM = wid >> 1, warpN = wid & 1;
    int h    = b / gx;
    int row0 = (b % gx) * 128, col0 = h * 64;

    __half2* f1h = reinterpret_cast<__half2*>(g_feat1v);
    float*   el1 = reinterpret_cast<float*>(g_el1v);
    float*   er1 = reinterpret_cast<float*>(g_er1v);

    if (tid < 128) { el_sh[tid] = 0.f; er_sh[tid] = 0.f; }

    float c[2][4][4];
#pragma unroll
    for (int mf = 0; mf < 2; mf++)
#pragma unroll
        for (int nf = 0; nf < 4; nf++)
#pragma unroll
            for (int j = 0; j < 4; j++) c[mf][nf][j] = 0.f;

    for (int kk = 0; kk < IN_F; kk += 32) {
#pragma unroll
        for (int i = 0; i < 4; i++) {
            int idx = tid + i * 256;
            int m = idx >> 3, kq = (idx & 7) * 4;
            int r = row0 + m;
            float4 v = (r < N) ? *(const float4*)&A[r * IN_F + kk + kq]
                               : make_float4(0.f, 0.f, 0.f, 0.f);
            As[m][kq + 0] = tf32r(v.x); As[m][kq + 1] = tf32r(v.y);
            As[m][kq + 2] = tf32r(v.z); As[m][kq + 3] = tf32r(v.w);
        }
#pragma unroll
        for (int i = 0; i < 2; i++) {
            int idx = tid + i * 256;
            int k = idx >> 4, nq = (idx & 15) * 4;
            float4 v = *(const float4*)&B[(kk + k) * HD + col0 + nq];
            Bs[k][nq + 0] = tf32r(v.x); Bs[k][nq + 1] = tf32r(v.y);
            Bs[k][nq + 2] = tf32r(v.z); Bs[k][nq + 3] = tf32r(v.w);
        }
        __syncthreads();

#pragma unroll
        for (int ks = 0; ks < 32; ks += 8) {
            uint32_t af[2][4], bf[4][2];
#pragma unroll
            for (int mf = 0; mf < 2; mf++) {
                int mbase = warpM * 32 + mf * 16;
                af[mf][0] = __float_as_uint(As[mbase + g    ][ks + tig    ]);
                af[mf][1] = __float_as_uint(As[mbase + g + 8][ks + tig    ]);
                af[mf][2] = __float_as_uint(As[mbase + g    ][ks + tig + 4]);
                af[mf][3] = __float_as_uint(As[mbase + g + 8][ks + tig + 4]);
            }
#pragma unroll
            for (int nf = 0; nf < 4; nf++) {
                int nbase = warpN * 32 + nf * 8;
                bf[nf][0] = __float_as_uint(Bs[ks + tig    ][nbase + g]);
                bf[nf][1] = __float_as_uint(Bs[ks + tig + 4][nbase + g]);
            }
#pragma unroll
            for (int mf = 0; mf < 2; mf++)
#pragma unroll
                for (int nf = 0; nf < 4; nf++) {
                    asm volatile(
                        "mma.sync.aligned.m16n8k8.row.col.f32.tf32.tf32.f32 "
                        "{%0,%1,%2,%3}, {%4,%5,%6,%7}, {%8,%9}, {%0,%1,%2,%3};"
                        : "+f"(c[mf][nf][0]), "+f"(c[mf][nf][1]),
                          "+f"(c[mf][nf][2]), "+f"(c[mf][nf][3])
                        : "r"(af[mf][0]), "r"(af[mf][1]),
                          "r"(af[mf][2]), "r"(af[mf][3]),
                          "r"(bf[nf][0]), "r"(bf[nf][1]));
                }
        }
        __syncthreads();
    }

    float alv[4][2], arv[4][2];
#pragma unroll
    for (int nf = 0; nf < 4; nf++)
#pragma unroll
        for (int j = 0; j < 2; j++) {
            int col = warpN * 32 + nf * 8 + 2 * tig + j;
            alv[nf][j] = al[h * D1 + col];
            arv[nf][j] = ar[h * D1 + col];
        }

#pragma unroll
    for (int mf = 0; mf < 2; mf++) {
        int lr0 = warpM * 32 + mf * 16 + g;
        int lr1 = lr0 + 8;
        int r0g = row0 + lr0, r1g = row0 + lr1;
        float el0 = 0.f, er0 = 0.f, el1v = 0.f, er1v = 0.f;
#pragma unroll
        for (int nf = 0; nf < 4; nf++) {
            int colw = warpN * 32 + nf * 8 + 2 * tig;
            int cp = (col0 + colw) >> 1;
            if (r0g < N)
                f1h[r0g * (HD/2) + cp] = __floats2half2_rn(c[mf][nf][0], c[mf][nf][1]);
            if (r1g < N)
                f1h[r1g * (HD/2) + cp] = __floats2half2_rn(c[mf][nf][2], c[mf][nf][3]);
            el0 += c[mf][nf][0] * alv[nf][0] + c[mf][nf][1] * alv[nf][1];
            er0 += c[mf][nf][0] * arv[nf][0] + c[mf][nf][1] * arv[nf][1];
            el1v += c[mf][nf][2] * alv[nf][0] + c[mf][nf][3] * alv[nf][1];
            er1v += c[mf][nf][2] * arv[nf][0] + c[mf][nf][3] * arv[nf][1];
        }
#pragma unroll
        for (int o = 1; o < 4; o <<= 1) {
            el0  += __shfl_xor_sync(0xffffffffu, el0,  o, 4);
            er0  += __shfl_xor_sync(0xffffffffu, er0,  o, 4);
            el1v += __shfl_xor_sync(0xffffffffu, el1v, o, 4);
            er1v += __shfl_xor_sync(0xffffffffu, er1v, o, 4);
        }
        if (tig == 0) {
            atomicAdd(&el_sh[lr0], el0);  atomicAdd(&er_sh[lr0], er0);
            atomicAdd(&el_sh[lr1], el1v); atomicAdd(&er_sh[lr1], er1v);
        }
    }
    __syncthreads();
    if (tid < 128) {
        int r = row0 + tid;
        if (r < N) {
            el1[r * NH + h] = el_sh[tid];
            er1[r * NH + h] = er_sh[tid];
        }
    }
}

// ---------------- layer1: softmax + agg + elu; warp-autonomous (R11) --------
__global__ void sfm_agg1_kernel(int N) {
    __shared__ int   s_sh[8][32];
    __shared__ float w_sh[8][NH][32];

    int tid = threadIdx.x;
    int wid = tid >> 5, lane = tid & 31;
    int n = blockIdx.x * 8 + wid;
    if (n >= N) return;

    int r0 = g_rowptr[n];
    int deg = g_rowptr[n + 1] - r0;
    float4 ern4 = g_er1v[n];

    float mx[NH] = {-INFINITY, -INFINITY, -INFINITY, -INFINITY};
    for (int i = lane; i < deg; i += 32) {
        int s = g_esrc[r0 + i];
        float4 el4 = g_el1v[s];
        float x0 = el4.x + ern4.x; x0 = (x0 > 0.f) ? x0 : NEG * x0;
        float x1 = el4.y + ern4.y; x1 = (x1 > 0.f) ? x1 : NEG * x1;
        float x2 = el4.z + ern4.z; x2 = (x2 > 0.f) ? x2 : NEG * x2;
        float x3 = el4.w + ern4.w; x3 = (x3 > 0.f) ? x3 : NEG * x3;
        mx[0] = fmaxf(mx[0], x0); mx[1] = fmaxf(mx[1], x1);
        mx[2] = fmaxf(mx[2], x2); mx[3] = fmaxf(mx[3], x3);
    }
#pragma unroll
    for (int h = 0; h < NH; h++)
#pragma unroll
        for (int o = 16; o; o >>= 1)
            mx[h] = fmaxf(mx[h], __shfl_xor_sync(0xffffffffu, mx[h], o));

    float den[NH] = {0.f, 0.f, 0.f, 0.f};
    for (int i = lane; i < deg; i += 32) {
        int s = g_esrc[r0 + i];
        float4 el4 = g_el1v[s];
        float x0 = el4.x + ern4.x; x0 = (x0 > 0.f) ? x0 : NEG * x0;
        float x1 = el4.y + ern4.y; x1 = (x1 > 0.f) ? x1 : NEG * x1;
        float x2 = el4.z + ern4.z; x2 = (x2 > 0.f) ? x2 : NEG * x2;
        float x3 = el4.w + ern4.w; x3 = (x3 > 0.f) ? x3 : NEG * x3;
        den[0] += __expf(x0 - mx[0]); den[1] += __expf(x1 - mx[1]);
        den[2] += __expf(x2 - mx[2]); den[3] += __expf(x3 - mx[3]);
    }
#pragma unroll
    for (int h = 0; h < NH; h++)
#pragma unroll
        for (int o = 16; o; o >>= 1)
            den[h] += __shfl_xor_sync(0xffffffffu, den[h], o);

    float idw[NH];
#pragma unroll
    for (int h = 0; h < NH; h++) idw[h] = 1.f / fmaxf(den[h], 1e-9f);

    int hme = lane >> 3;
    float acc[8] = {};

    for (int i0 = 0; i0 < deg; i0 += 32) {
        int cnt = min(32, deg - i0);
        if (lane < cnt) {
            int s = g_esrc[r0 + i0 + lane];
            s_sh[wid][lane] = s;
            float4 el4 = g_el1v[s];
            float x0 = el4.x + ern4.x; x0 = (x0 > 0.f) ? x0 : NEG * x0;
            float x1 = el4.y + ern4.y; x1 = (x1 > 0.f) ? x1 : NEG * x1;
            float x2 = el4.z + ern4.z; x2 = (x2 > 0.f) ? x2 : NEG * x2;
            float x3 = el4.w + ern4.w; x3 = (x3 > 0.f) ? x3 : NEG * x3;
            w_sh[wid][0][lane] = __expf(x0 - mx[0]) * idw[0];
            w_sh[wid][1][lane] = __expf(x1 - mx[1]) * idw[1];
            w_sh[wid][2][lane] = __expf(x2 - mx[2]) * idw[2];
            w_sh[wid][3][lane] = __expf(x3 - mx[3]) * idw[3];
        }
        __syncwarp();
        for (int i = 0; i < cnt; i++) {
            int s = s_sh[wid][i];
            float w = w_sh[wid][hme][i];
            uint4 raw = g_feat1v[s * 32 + lane];
            float2 p0 = __half22float2(*reinterpret_cast<__half2*>(&raw.x));
            float2 p1 = __half22float2(*reinterpret_cast<__half2*>(&raw.y));
            float2 p2 = __half22float2(*reinterpret_cast<__half2*>(&raw.z));
            float2 p3 = __half22float2(*reinterpret_cast<__half2*>(&raw.w));
            acc[0] += w * p0.x; acc[1] += w * p0.y;
            acc[2] += w * p1.x; acc[3] += w * p1.y;
            acc[4] += w * p2.x; acc[5] += w * p2.y;
            acc[6] += w * p3.x; acc[7] += w * p3.y;
        }
        __syncwarp();
    }

    float o[8];
#pragma unroll
    for (int q = 0; q < 8; q++)
        o[q] = (acc[q] > 0.f) ? acc[q] : expm1f(acc[q]);
    g_h2v[n * 64 + lane * 2]     = make_float4(o[0], o[1], o[2], o[3]);
    g_h2v[n * 64 + lane * 2 + 1] = make_float4(o[4], o[5], o[6], o[7]);
}

// ---------------- layer2 GEMM (tf32 mma) + attention dots -------------------
__global__ void gemm2_attn_kernel(const float* __restrict__ W2,
                                  const float* __restrict__ al2,
                                  const float* __restrict__ ar2, int N) {
    __shared__ float As[128][36];
    __shared__ float Bs[32][72];
    __shared__ float el_sh[128], er_sh[128];

    int tid  = threadIdx.x;
    int wid  = tid >> 5, lane = tid & 31;
    int g    = lane >> 2, tig = lane & 3;
    int warpM = wid >> 1, warpN = wid & 1;
    int row0 = blockIdx.x * 128;

    if (tid < 128) { el_sh[tid] = 0.f; er_sh[tid] = 0.f; }

    float c[2][4][4];
#pragma unroll
    for (int mf = 0; mf < 2; mf++)
#pragma unroll
        for (int nf = 0; nf < 4; nf++)
#pragma unroll
            for (int j = 0; j < 4; j++) c[mf][nf][j] = 0.f;

    for (int kk = 0; kk < HD; kk += 32) {
#pragma unroll
        for (int i = 0; i < 4; i++) {
            int idx = tid + i * 256;
            int m = idx >> 3, kq = (idx & 7) * 4;
            int r = row0 + m;
            float4 v = (r < N) ? g_h2v[r * 64 + (kk + kq) / 4]
                               : make_float4(0.f, 0.f, 0.f, 0.f);
            As[m][kq + 0] = tf32r(v.x); As[m][kq + 1] = tf32r(v.y);
            As[m][kq + 2] = tf32r(v.z); As[m][kq + 3] = tf32r(v.w);
        }
#pragma unroll
        for (int i = 0; i < 8; i++) {
            int idx = tid + i * 256;
            int k = idx >> 6, nn = idx & 63;
            Bs[k][nn] = (nn < OUTF) ? tf32r(W2[(kk + k) * OUTF + nn]) : 0.f;
        }
        __syncthreads();

#pragma unroll
        for (int ks = 0; ks < 32; ks += 8) {
            uint32_t af[2][4], bf[4][2];
#pragma unroll
            for (int mf = 0; mf < 2; mf++) {
                int mbase = warpM * 32 + mf * 16;
                af[mf][0] = __float_as_uint(As[mbase + g    ][ks + tig    ]);
                af[mf][1] = __float_as_uint(As[mbase + g + 8][ks + tig    ]);
                af[mf][2] = __float_as_uint(As[mbase + g    ][ks + tig + 4]);
                af[mf][3] = __float_as_uint(As[mbase + g + 8][ks + tig + 4]);
            }
#pragma unroll
            for (int nf = 0; nf < 4; nf++) {
                int nbase = warpN * 32 + nf * 8;
                bf[nf][0] = __float_as_uint(Bs[ks + tig    ][nbase + g]);
                bf[nf][1] = __float_as_uint(Bs[ks + tig + 4][nbase + g]);
            }
#pragma unroll
            for (int mf = 0; mf < 2; mf++)
#pragma unroll
                for (int nf = 0; nf < 4; nf++) {
                    asm volatile(
                        "mma.sync.aligned.m16n8k8.row.col.f32.tf32.tf32.f32 "
                        "{%0,%1,%2,%3}, {%4,%5,%6,%7}, {%8,%9}, {%0,%1,%2,%3};"
                        : "+f"(c[mf][nf][0]), "+f"(c[mf][nf][1]),
                          "+f"(c[mf][nf][2]), "+f"(c[mf][nf][3])
                        : "r"(af[mf][0]), "r"(af[mf][1]),
                          "r"(af[mf][2]), "r"(af[mf][3]),
                          "r"(bf[nf][0]), "r"(bf[nf][1]));
                }
        }
        __syncthreads();
    }

    float alv[4][2], arv[4][2];
#pragma unroll
    for (int nf = 0; nf < 4; nf++)
#pragma unroll
        for (int j = 0; j < 2; j++) {
            int col = warpN * 32 + nf * 8 + 2 * tig + j;
            alv[nf][j] = (col < OUTF) ? al2[col] : 0.f;
            arv[nf][j] = (col < OUTF) ? ar2[col] : 0.f;
        }

#pragma unroll
    for (int mf = 0; mf < 2; mf++) {
        int lr0 = warpM * 32 + mf * 16 + g;
        int lr1 = lr0 + 8;
        int r0g = row0 + lr0, r1g = row0 + lr1;
        float el0 = 0.f, er0 = 0.f, el1v = 0.f, er1v = 0.f;
#pragma unroll
        for (int nf = 0; nf < 4; nf++) {
            int colw = warpN * 32 + nf * 8 + 2 * tig;
#pragma unroll
            for (int j = 0; j < 2; j++) {
                int col = colw + j;
                if (col < OUTF) {
                    if (r0g < N) g_feat2[r0g * OUTP + col] = c[mf][nf][j];
                    if (r1g < N) g_feat2[r1g * OUTP + col] = c[mf][nf][2 + j];
                }
            }
            el0 += c[mf][nf][0] * alv[nf][0] + c[mf][nf][1] * alv[nf][1];
            er0 += c[mf][nf][0] * arv[nf][0] + c[mf][nf][1] * arv[nf][1];
            el1v += c[mf][nf][2] * alv[nf][0] + c[mf][nf][3] * alv[nf][1];
            er1v += c[mf][nf][2] * arv[nf][0] + c[mf][nf][3] * arv[nf][1];
        }
#pragma unroll
        for (int o = 1; o < 4; o <<= 1) {
            el0  += __shfl_xor_sync(0xffffffffu, el0,  o, 4);
            er0  += __shfl_xor_sync(0xffffffffu, er0,  o, 4);
            el1v += __shfl_xor_sync(0xffffffffu, el1v, o, 4);
            er1v += __shfl_xor_sync(0xffffffffu, er1v, o, 4);
        }
        if (tig == 0) {
            atomicAdd(&el_sh[lr0], el0);  atomicAdd(&er_sh[lr0], er0);
            atomicAdd(&el_sh[lr1], el1v); atomicAdd(&er_sh[lr1], er1v);
        }
    }
    __syncthreads();
    if (tid < 128) {
        int r = row0 + tid;
        if (r < N) {
            g_el2[r] = el_sh[tid];
            g_er2[r] = er_sh[tid];
        }
    }
}

// ---------------- layer2: softmax + agg + log_softmax (warp per node) -------
__global__ void agg2_ls_kernel(float* __restrict__ out, int N) {
    int warp = threadIdx.x >> 5;
    int lane = threadIdx.x & 31;
    int n = blockIdx.x * 4 + warp;
    if (n >= N) return;
    int r0 = g_rowptr[n];
    int deg = g_rowptr[n + 1] - r0;
    float ern = g_er2[n];

    float mx = -INFINITY;
    for (int i = lane; i < deg; i += 32) {
        int s = g_esrc[r0 + i];
        float x = g_el2[s] + ern;
        x = (x > 0.f) ? x : NEG * x;
        mx = fmaxf(mx, x);
    }
#pragma unroll
    for (int o = 16; o; o >>= 1)
        mx = fmaxf(mx, __shfl_xor_sync(0xffffffffu, mx, o));

    float den = 0.f;
    for (int i = lane; i < deg; i += 32) {
        int s = g_esrc[r0 + i];
        float x = g_el2[s] + ern;
        x = (x > 0.f) ? x : NEG * x;
        den += __expf(x - mx);
    }
#pragma unroll
    for (int o = 16; o; o >>= 1)
        den += __shfl_xor_sync(0xffffffffu, den, o);
    den = fmaxf(den, 1e-9f);

    bool hi = (lane + 32) < OUTF;
    float a0 = 0.f, a1 = 0.f;
    for (int i = 0; i < deg; i++) {
        int s = g_esrc[r0 + i];
        float x = g_el2[s] + ern;
        x = (x > 0.f) ? x : NEG * x;
        float w = __expf(x - mx);
        a0 += w * g_feat2[s * OUTP + lane];
        if (hi) a1 += w * g_feat2[s * OUTP + lane + 32];
    }
    a0 /= den;
    a1 /= den;

    float v0 = a0;
    float v1 = hi ? a1 : -INFINITY;
    float m2 = fmaxf(v0, v1);
#pragma unroll
    for (int o = 16; o; o >>= 1)
        m2 = fmaxf(m2, __shfl_xor_sync(0xffffffffu, m2, o));
    float s_ = expf(v0 - m2) + (hi ? expf(v1 - m2) : 0.f);
#pragma unroll
    for (int o = 16; o; o >>= 1)
        s_ += __shfl_xor_sync(0xffffffffu, s_, o);
    float ls = logf(s_) + m2;
    out[n * OUTF + lane] = v0 - ls;
    if (hi) out[n * OUTF + lane + 32] = v1 - ls;
}

// ---------------- launch ----------------
extern "C" void kernel_launch(void* const* d_in, const int* in_sizes, int n_in,
                              void* d_out, int out_size) {
    const float* features = (const float*)d_in[0];
    const int*   src      = (const int*)d_in[1];
    const int*   dst      = (const int*)d_in[2];
    const float* W1       = (const float*)d_in[3];
    const float* al1      = (const float*)d_in[4];
    const float* ar1      = (const float*)d_in[5];
    const float* W2       = (const float*)d_in[6];
    const float* al2      = (const float*)d_in[7];
    const float* ar2      = (const float*)d_in[8];
    float* out = (float*)d_out;

    int N = in_sizes[0] / IN_F;   // 10000
    int E = in_sizes[1];          // 320000
    if (N > N_NODES) N = N_NODES;
    if (E > N_EDGES) E = N_EDGES;

    int e4blocks = (E / 4 + 255) / 256 + 1;
    count_kernel<<<e4blocks, 256>>>(dst, E);
    scan_kernel<<<1, 1024>>>();

    int gx = (N + 127) / 128;
    gemm1_scatter_kernel<<<gx * NH + e4blocks, 256>>>(
        features, W1, al1, ar1, src, dst, N, E, gx);

    sfm_agg1_kernel<<<(N + 7) / 8, 256>>>(N);
    gemm2_attn_kernel<<<(N + 127) / 128, 256>>>(W2, al2, ar2, N);
    agg2_ls_kernel<<<(N + 3) / 4, 128>>>(out, N);
}

// round 16
// speedup vs baseline: 1.5587x; 1.0831x over previous
#include <cuda_runtime.h>
#include <cuda_fp16.h>
#include <math.h>
#include <stdint.h>

#define N_NODES 10000
#define N_EDGES 320000
#define IN_F    256
#define HD      256
#define NH      4
#define D1      64
#define OUTF    47
#define OUTP    48
#define NEG     0.2f

// ---------------- scratch: vector-typed so 16B alignment is guaranteed ------
__device__ uint4  g_feat1v[N_NODES * 32];   // 256 fp16 ch = 32 uint4 per node
__device__ float4 g_h2v   [N_NODES * 64];   // 256 fp32  = 64 float4 per node
__device__ float4 g_el1v  [N_NODES];        // 4 heads
__device__ float4 g_er1v  [N_NODES];
__device__ float  g_feat2 [N_NODES * OUTP];
__device__ float  g_el2   [N_NODES];
__device__ float  g_er2   [N_NODES];

__device__ int   g_deg   [N_NODES];   // zero at launch entry (scan re-zeroes)
__device__ int   g_rowptr[N_NODES + 1];
__device__ int   g_cursor[N_NODES];   // zeroed by scan before scatter
__device__ int   g_esrc  [N_EDGES];

__device__ __forceinline__ float tf32r(float x) {
    uint32_t u;
    asm("cvt.rna.tf32.f32 %0, %1;" : "=r"(u) : "f"(x));
    return __uint_as_float(u);
}

// accumulate 8 fp16 channels (one uint4) scaled by w into acc[8]
__device__ __forceinline__ void acc8(float* acc, uint4 q, float w) {
    float2 p0 = __half22float2(*reinterpret_cast<__half2*>(&q.x));
    float2 p1 = __half22float2(*reinterpret_cast<__half2*>(&q.y));
    float2 p2 = __half22float2(*reinterpret_cast<__half2*>(&q.z));
    float2 p3 = __half22float2(*reinterpret_cast<__half2*>(&q.w));
    acc[0] += w * p0.x; acc[1] += w * p0.y;
    acc[2] += w * p1.x; acc[3] += w * p1.y;
    acc[4] += w * p2.x; acc[5] += w * p2.y;
    acc[6] += w * p3.x; acc[7] += w * p3.y;
}

// ---------------- CSR: count ----------------
__global__ void count_kernel(const int* __restrict__ dst, int E) {
    int e4 = (blockIdx.x * blockDim.x + threadIdx.x) * 4;
    if (e4 + 3 < E) {
        int4 d = *(const int4*)&dst[e4];
        atomicAdd(&g_deg[d.x], 1); atomicAdd(&g_deg[d.y], 1);
        atomicAdd(&g_deg[d.z], 1); atomicAdd(&g_deg[d.w], 1);
    } else {
        for (int e = e4; e < E; e++) atomicAdd(&g_deg[dst[e]], 1);
    }
}

// ---------------- CSR: scan (also resets g_deg & g_cursor for reuse) --------
__global__ void scan_kernel() {
    __shared__ int part[1024];
    const int PER = (N_NODES + 1023) / 1024;   // 10
    int t = threadIdx.x;
    int base = t * PER;
    int loc[PER];
    int sum = 0;
#pragma unroll
    for (int i = 0; i < PER; i++) {
        int idx = base + i;
        int v = (idx < N_NODES) ? g_deg[idx] : 0;
        sum += v;
        loc[i] = sum;
        if (idx < N_NODES) { g_deg[idx] = 0; g_cursor[idx] = 0; }
    }
    part[t] = sum;
    __syncthreads();
    for (int off = 1; off < 1024; off <<= 1) {
        int add = (t >= off) ? part[t - off] : 0;
        __syncthreads();
        part[t] += add;
        __syncthreads();
    }
    int offset = (t > 0) ? part[t - 1] : 0;
#pragma unroll
    for (int i = 0; i < PER; i++) {
        int idx = base + i;
        if (idx < N_NODES) g_rowptr[idx + 1] = offset + loc[i];
    }
    if (t == 0) g_rowptr[0] = 0;
}

// ---------------- FUSED: gemm1 (128x64, head/block, reg-prefetch) ∥ scatter --
__global__ void gemm1_scatter_kernel(const float* __restrict__ A,
                                     const float* __restrict__ B,
                                     const float* __restrict__ al,
                                     const float* __restrict__ ar,
                                     const int* __restrict__ src,
                                     const int* __restrict__ dst,
                                     int N, int E, int gx) {
    __shared__ float As[128][36];
    __shared__ float Bs[32][72];
    __shared__ float el_sh[128], er_sh[128];

    int b = blockIdx.x;
    int tid = threadIdx.x;

    if (b >= gx * NH) {
        // ---- scatter branch: 4 edges/thread ----
        int sb = b - gx * NH;
        int e4 = (sb * blockDim.x + tid) * 4;
        if (e4 + 3 < E) {
            int4 s = *(const int4*)&src[e4];
            int4 d = *(const int4*)&dst[e4];
            g_esrc[g_rowptr[d.x] + atomicAdd(&g_cursor[d.x], 1)] = s.x;
            g_esrc[g_rowptr[d.y] + atomicAdd(&g_cursor[d.y], 1)] = s.y;
            g_esrc[g_rowptr[d.z] + atomicAdd(&g_cursor[d.z], 1)] = s.z;
            g_esrc[g_rowptr[d.w] + atomicAdd(&g_cursor[d.w], 1)] = s.w;
        } else {
            for (int e = e4; e < E; e++) {
                int d = dst[e];
                g_esrc[g_rowptr[d] + atomicAdd(&g_cursor[d], 1)] = src[e];
            }
        }
        return;
    }

    // ---- GEMM1 branch ----
    int wid  = tid >> 5, lane = tid & 31;
    int g    = lane >> 2, tig = lane & 3;
    int warpM = wid >> 1, warpN = wid & 1;
    int h    = b / gx;
    int row0 = (b % gx) * 128, col0 = h * 64;

    __half2* f1h = reinterpret_cast<__half2*>(g_feat1v);
    float*   el1 = reinterpret_cast<float*>(g_el1v);
    float*   er1 = reinterpret_cast<float*>(g_er1v);

    if (tid < 128) { el_sh[tid] = 0.f; er_sh[tid] = 0.f; }

    const float4 z4 = make_float4(0.f, 0.f, 0.f, 0.f);
    int amIdx[4], akIdx[4];
#pragma unroll
    for (int i = 0; i < 4; i++) {
        int idx = tid + i * 256;
        amIdx[i] = idx >> 3; akIdx[i] = (idx & 7) * 4;
    }
    int bkIdx[2], bnIdx[2];
#pragma unroll
    for (int i = 0; i < 2; i++) {
        int idx = tid + i * 256;
        bkIdx[i] = idx >> 4; bnIdx[i] = (idx & 15) * 4;
    }

    float c[2][4][4];
#pragma unroll
    for (int mf = 0; mf < 2; mf++)
#pragma unroll
        for (int nf = 0; nf < 4; nf++)
#pragma unroll
            for (int j = 0; j < 4; j++) c[mf][nf][j] = 0.f;

    // prologue: load tile kk=0 into regs, commit to smem
    float4 aP[4], bP[2];
#pragma unroll
    for (int i = 0; i < 4; i++) {
        int r = row0 + amIdx[i];
        aP[i] = (r < N) ? *(const float4*)&A[r * IN_F + akIdx[i]] : z4;
    }
#pragma unroll
    for (int i = 0; i < 2; i++)
        bP[i] = *(const float4*)&B[bkIdx[i] * HD + col0 + bnIdx[i]];
#pragma unroll
    for (int i = 0; i < 4; i++) {
        As[amIdx[i]][akIdx[i] + 0] = tf32r(aP[i].x);
        As[amIdx[i]][akIdx[i] + 1] = tf32r(aP[i].y);
        As[amIdx[i]][akIdx[i] + 2] = tf32r(aP[i].z);
        As[amIdx[i]][akIdx[i] + 3] = tf32r(aP[i].w);
    }
#pragma unroll
    for (int i = 0; i < 2; i++) {
        Bs[bkIdx[i]][bnIdx[i] + 0] = tf32r(bP[i].x);
        Bs[bkIdx[i]][bnIdx[i] + 1] = tf32r(bP[i].y);
        Bs[bkIdx[i]][bnIdx[i] + 2] = tf32r(bP[i].z);
        Bs[bkIdx[i]][bnIdx[i] + 3] = tf32r(bP[i].w);
    }
    __syncthreads();

    for (int kk = 0; kk < IN_F; kk += 32) {
        bool nxt = (kk + 32) < IN_F;
        float4 aN[4], bN[2];
        if (nxt) {      // prefetch next tile (LDGs overlap the mma below)
#pragma unroll
            for (int i = 0; i < 4; i++) {
                int r = row0 + amIdx[i];
                aN[i] = (r < N) ? *(const float4*)&A[r * IN_F + kk + 32 + akIdx[i]] : z4;
            }
#pragma unroll
            for (int i = 0; i < 2; i++)
                bN[i] = *(const float4*)&B[(kk + 32 + bkIdx[i]) * HD + col0 + bnIdx[i]];
        }

#pragma unroll
        for (int ks = 0; ks < 32; ks += 8) {
            uint32_t af[2][4], bf[4][2];
#pragma unroll
            for (int mf = 0; mf < 2; mf++) {
                int mbase = warpM * 32 + mf * 16;
                af[mf][0] = __float_as_uint(As[mbase + g    ][ks + tig    ]);
                af[mf][1] = __float_as_uint(As[mbase + g + 8][ks + tig    ]);
                af[mf][2] = __float_as_uint(As[mbase + g    ][ks + tig + 4]);
                af[mf][3] = __float_as_uint(As[mbase + g + 8][ks + tig + 4]);
            }
#pragma unroll
            for (int nf = 0; nf < 4; nf++) {
                int nbase = warpN * 32 + nf * 8;
                bf[nf][0] = __float_as_uint(Bs[ks + tig    ][nbase + g]);
                bf[nf][1] = __float_as_uint(Bs[ks + tig + 4][nbase + g]);
            }
#pragma unroll
            for (int mf = 0; mf < 2; mf++)
#pragma unroll
                for (int nf = 0; nf < 4; nf++) {
                    asm volatile(
                        "mma.sync.aligned.m16n8k8.row.col.f32.tf32.tf32.f32 "
                        "{%0,%1,%2,%3}, {%4,%5,%6,%7}, {%8,%9}, {%0,%1,%2,%3};"
                        : "+f"(c[mf][nf][0]), "+f"(c[mf][nf][1]),
                          "+f"(c[mf][nf][2]), "+f"(c[mf][nf][3])
                        : "r"(af[mf][0]), "r"(af[mf][1]),
                          "r"(af[mf][2]), "r"(af[mf][3]),
                          "r"(bf[nf][0]), "r"(bf[nf][1]));
                }
        }
        __syncthreads();
        if (nxt) {
#pragma unroll
            for (int i = 0; i < 4; i++) {
                As[amIdx[i]][akIdx[i] + 0] = tf32r(aN[i].x);
                As[amIdx[i]][akIdx[i] + 1] = tf32r(aN[i].y);
                As[amIdx[i]][akIdx[i] + 2] = tf32r(aN[i].z);
                As[amIdx[i]][akIdx[i] + 3] = tf32r(aN[i].w);
            }
#pragma unroll
            for (int i = 0; i < 2; i++) {
                Bs[bkIdx[i]][bnIdx[i] + 0] = tf32r(bN[i].x);
                Bs[bkIdx[i]][bnIdx[i] + 1] = tf32r(bN[i].y);
                Bs[bkIdx[i]][bnIdx[i] + 2] = tf32r(bN[i].z);
                Bs[bkIdx[i]][bnIdx[i] + 3] = tf32r(bN[i].w);
            }
            __syncthreads();
        }
    }

    float alv[4][2], arv[4][2];
#pragma unroll
    for (int nf = 0; nf < 4; nf++)
#pragma unroll
        for (int j = 0; j < 2; j++) {
            int col = warpN * 32 + nf * 8 + 2 * tig + j;
            alv[nf][j] = al[h * D1 + col];
            arv[nf][j] = ar[h * D1 + col];
        }

#pragma unroll
    for (int mf = 0; mf < 2; mf++) {
        int lr0 = warpM * 32 + mf * 16 + g;
        int lr1 = lr0 + 8;
        int r0g = row0 + lr0, r1g = row0 + lr1;
        float el0 = 0.f, er0 = 0.f, el1v = 0.f, er1v = 0.f;
#pragma unroll
        for (int nf = 0; nf < 4; nf++) {
            int colw = warpN * 32 + nf * 8 + 2 * tig;
            int cp = (col0 + colw) >> 1;
            if (r0g < N)
                f1h[r0g * (HD/2) + cp] = __floats2half2_rn(c[mf][nf][0], c[mf][nf][1]);
            if (r1g < N)
                f1h[r1g * (HD/2) + cp] = __floats2half2_rn(c[mf][nf][2], c[mf][nf][3]);
            el0 += c[mf][nf][0] * alv[nf][0] + c[mf][nf][1] * alv[nf][1];
            er0 += c[mf][nf][0] * arv[nf][0] + c[mf][nf][1] * arv[nf][1];
            el1v += c[mf][nf][2] * alv[nf][0] + c[mf][nf][3] * alv[nf][1];
            er1v += c[mf][nf][2] * arv[nf][0] + c[mf][nf][3] * arv[nf][1];
        }
#pragma unroll
        for (int o = 1; o < 4; o <<= 1) {
            el0  += __shfl_xor_sync(0xffffffffu, el0,  o, 4);
            er0  += __shfl_xor_sync(0xffffffffu, er0,  o, 4);
            el1v += __shfl_xor_sync(0xffffffffu, el1v, o, 4);
            er1v += __shfl_xor_sync(0xffffffffu, er1v, o, 4);
        }
        if (tig == 0) {
            atomicAdd(&el_sh[lr0], el0);  atomicAdd(&er_sh[lr0], er0);
            atomicAdd(&el_sh[lr1], el1v); atomicAdd(&er_sh[lr1], er1v);
        }
    }
    __syncthreads();
    if (tid < 128) {
        int r = row0 + tid;
        if (r < N) {
            el1[r * NH + h] = el_sh[tid];
            er1[r * NH + h] = er_sh[tid];
        }
    }
}

// ---------------- layer1: softmax + agg + elu; MLP-4 gather -----------------
__global__ void sfm_agg1_kernel(int N) {
    __shared__ int   s_sh[8][32];
    __shared__ float w_sh[8][NH][32];

    int tid = threadIdx.x;
    int wid = tid >> 5, lane = tid & 31;
    int n = blockIdx.x * 8 + wid;
    if (n >= N) return;

    int r0 = g_rowptr[n];
    int deg = g_rowptr[n + 1] - r0;
    float4 ern4 = g_er1v[n];

    float mx[NH] = {-INFINITY, -INFINITY, -INFINITY, -INFINITY};
    for (int i = lane; i < deg; i += 32) {
        int s = g_esrc[r0 + i];
        float4 el4 = g_el1v[s];
        float x0 = el4.x + ern4.x; x0 = (x0 > 0.f) ? x0 : NEG * x0;
        float x1 = el4.y + ern4.y; x1 = (x1 > 0.f) ? x1 : NEG * x1;
        float x2 = el4.z + ern4.z; x2 = (x2 > 0.f) ? x2 : NEG * x2;
        float x3 = el4.w + ern4.w; x3 = (x3 > 0.f) ? x3 : NEG * x3;
        mx[0] = fmaxf(mx[0], x0); mx[1] = fmaxf(mx[1], x1);
        mx[2] = fmaxf(mx[2], x2); mx[3] = fmaxf(mx[3], x3);
    }
#pragma unroll
    for (int h = 0; h < NH; h++)
#pragma unroll
        for (int o = 16; o; o >>= 1)
            mx[h] = fmaxf(mx[h], __shfl_xor_sync(0xffffffffu, mx[h], o));

    float den[NH] = {0.f, 0.f, 0.f, 0.f};
    for (int i = lane; i < deg; i += 32) {
        int s = g_esrc[r0 + i];
        float4 el4 = g_el1v[s];
        float x0 = el4.x + ern4.x; x0 = (x0 > 0.f) ? x0 : NEG * x0;
        float x1 = el4.y + ern4.y; x1 = (x1 > 0.f) ? x1 : NEG * x1;
        float x2 = el4.z + ern4.z; x2 = (x2 > 0.f) ? x2 : NEG * x2;
        float x3 = el4.w + ern4.w; x3 = (x3 > 0.f) ? x3 : NEG * x3;
        den[0] += __expf(x0 - mx[0]); den[1] += __expf(x1 - mx[1]);
        den[2] += __expf(x2 - mx[2]); den[3] += __expf(x3 - mx[3]);
    }
#pragma unroll
    for (int h = 0; h < NH; h++)
#pragma unroll
        for (int o = 16; o; o >>= 1)
            den[h] += __shfl_xor_sync(0xffffffffu, den[h], o);

    float idw[NH];
#pragma unroll
    for (int h = 0; h < NH; h++) idw[h] = 1.f / fmaxf(den[h], 1e-9f);

    int hme = lane >> 3;
    float acc[8] = {};

    for (int i0 = 0; i0 < deg; i0 += 32) {
        int cnt = min(32, deg - i0);
        if (lane < cnt) {
            int s = g_esrc[r0 + i0 + lane];
            s_sh[wid][lane] = s;
            float4 el4 = g_el1v[s];
            float x0 = el4.x + ern4.x; x0 = (x0 > 0.f) ? x0 : NEG * x0;
            float x1 = el4.y + ern4.y; x1 = (x1 > 0.f) ? x1 : NEG * x1;
            float x2 = el4.z + ern4.z; x2 = (x2 > 0.f) ? x2 : NEG * x2;
            float x3 = el4.w + ern4.w; x3 = (x3 > 0.f) ? x3 : NEG * x3;
            w_sh[wid][0][lane] = __expf(x0 - mx[0]) * idw[0];
            w_sh[wid][1][lane] = __expf(x1 - mx[1]) * idw[1];
            w_sh[wid][2][lane] = __expf(x2 - mx[2]) * idw[2];
            w_sh[wid][3][lane] = __expf(x3 - mx[3]) * idw[3];
        }
        __syncwarp();
        int i = 0;
        // MLP-4: issue 4 independent LDG.128 before the math
        for (; i + 4 <= cnt; i += 4) {
            int s0 = s_sh[wid][i + 0], s1 = s_sh[wid][i + 1];
            int s2 = s_sh[wid][i + 2], s3 = s_sh[wid][i + 3];
            uint4 q0 = g_feat1v[s0 * 32 + lane];
            uint4 q1 = g_feat1v[s1 * 32 + lane];
            uint4 q2 = g_feat1v[s2 * 32 + lane];
            uint4 q3 = g_feat1v[s3 * 32 + lane];
            float w0 = w_sh[wid][hme][i + 0], w1 = w_sh[wid][hme][i + 1];
            float w2 = w_sh[wid][hme][i + 2], w3 = w_sh[wid][hme][i + 3];
            acc8(acc, q0, w0); acc8(acc, q1, w1);
            acc8(acc, q2, w2); acc8(acc, q3, w3);
        }
        for (; i < cnt; i++) {
            uint4 q = g_feat1v[s_sh[wid][i] * 32 + lane];
            acc8(acc, q, w_sh[wid][hme][i]);
        }
        __syncwarp();
    }

    float o[8];
#pragma unroll
    for (int q = 0; q < 8; q++)
        o[q] = (acc[q] > 0.f) ? acc[q] : expm1f(acc[q]);
    g_h2v[n * 64 + lane * 2]     = make_float4(o[0], o[1], o[2], o[3]);
    g_h2v[n * 64 + lane * 2 + 1] = make_float4(o[4], o[5], o[6], o[7]);
}

// ---------------- layer2 GEMM (tf32 mma, reg-prefetch) + attention dots -----
__global__ void gemm2_attn_kernel(const float* __restrict__ W2,
                                  const float* __restrict__ al2,
                                  const float* __restrict__ ar2, int N) {
    __shared__ float As[128][36];
    __shared__ float Bs[32][72];
    __shared__ float el_sh[128], er_sh[128];

    int tid  = threadIdx.x;
    int wid  = tid >> 5, lane = tid & 31;
    int g    = lane >> 2, tig = lane & 3;
    int warpM = wid >> 1, warpN = wid & 1;
    int row0 = blockIdx.x * 128;

    if (tid < 128) { el_sh[tid] = 0.f; er_sh[tid] = 0.f; }

    const float4 z4 = make_float4(0.f, 0.f, 0.f, 0.f);
    int amIdx[4], akIdx[4];
#pragma unroll
    for (int i = 0; i < 4; i++) {
        int idx = tid + i * 256;
        amIdx[i] = idx >> 3; akIdx[i] = (idx & 7) * 4;
    }

    float c[2][4][4];
#pragma unroll
    for (int mf = 0; mf < 2; mf++)
#pragma unroll
        for (int nf = 0; nf < 4; nf++)
#pragma unroll
            for (int j = 0; j < 4; j++) c[mf][nf][j] = 0.f;

    // prologue tile kk=0
    float4 aP[4];
    float  bPv[8];
#pragma unroll
    for (int i = 0; i < 4; i++) {
        int r = row0 + amIdx[i];
        aP[i] = (r < N) ? g_h2v[r * 64 + akIdx[i] / 4] : z4;
    }
#pragma unroll
    for (int i = 0; i < 8; i++) {
        int idx = tid + i * 256;
        int k = idx >> 6, nn = idx & 63;
        bPv[i] = (nn < OUTF) ? W2[k * OUTF + nn] : 0.f;
    }
#pragma unroll
    for (int i = 0; i < 4; i++) {
        As[amIdx[i]][akIdx[i] + 0] = tf32r(aP[i].x);
        As[amIdx[i]][akIdx[i] + 1] = tf32r(aP[i].y);
        As[amIdx[i]][akIdx[i] + 2] = tf32r(aP[i].z);
        As[amIdx[i]][akIdx[i] + 3] = tf32r(aP[i].w);
    }
#pragma unroll
    for (int i = 0; i < 8; i++) {
        int idx = tid + i * 256;
        Bs[idx >> 6][idx & 63] = tf32r(bPv[i]);
    }
    __syncthreads();

    for (int kk = 0; kk < HD; kk += 32) {
        bool nxt = (kk + 32) < HD;
        float4 aN[4];
        float  bNv[8];
        if (nxt) {
#pragma unroll
            for (int i = 0; i < 4; i++) {
                int r = row0 + amIdx[i];
                aN[i] = (r < N) ? g_h2v[r * 64 + (kk + 32 + akIdx[i]) / 4] : z4;
            }
#pragma unroll
            for (int i = 0; i < 8; i++) {
                int idx = tid + i * 256;
                int k = idx >> 6, nn = idx & 63;
                bNv[i] = (nn < OUTF) ? W2[(kk + 32 + k) * OUTF + nn] : 0.f;
            }
        }

#pragma unroll
        for (int ks = 0; ks < 32; ks += 8) {
            uint32_t af[2][4], bf[4][2];
#pragma unroll
            for (int mf = 0; mf < 2; mf++) {
                int mbase = warpM * 32 + mf * 16;
                af[mf][0] = __float_as_uint(As[mbase + g    ][ks + tig    ]);
                af[mf][1] = __float_as_uint(As[mbase + g + 8][ks + tig    ]);
                af[mf][2] = __float_as_uint(As[mbase + g    ][ks + tig + 4]);
                af[mf][3] = __float_as_uint(As[mbase + g + 8][ks + tig + 4]);
            }
#pragma unroll
            for (int nf = 0; nf < 4; nf++) {
                int nbase = warpN * 32 + nf * 8;
                bf[nf][0] = __float_as_uint(Bs[ks + tig    ][nbase + g]);
                bf[nf][1] = __float_as_uint(Bs[ks + tig + 4][nbase + g]);
            }
#pragma unroll
            for (int mf = 0; mf < 2; mf++)
#pragma unroll
                for (int nf = 0; nf < 4; nf++) {
                    asm volatile(
                        "mma.sync.aligned.m16n8k8.row.col.f32.tf32.tf32.f32 "
                        "{%0,%1,%2,%3}, {%4,%5,%6,%7}, {%8,%9}, {%0,%1,%2,%3};"
                        : "+f"(c[mf][nf][0]), "+f"(c[mf][nf][1]),
                          "+f"(c[mf][nf][2]), "+f"(c[mf][nf][3])
                        : "r"(af[mf][0]), "r"(af[mf][1]),
                          "r"(af[mf][2]), "r"(af[mf][3]),
                          "r"(bf[nf][0]), "r"(bf[nf][1]));
                }
        }
        __syncthreads();
        if (nxt) {
#pragma unroll
            for (int i = 0; i < 4; i++) {
                As[amIdx[i]][akIdx[i] + 0] = tf32r(aN[i].x);
                As[amIdx[i]][akIdx[i] + 1] = tf32r(aN[i].y);
                As[amIdx[i]][akIdx[i] + 2] = tf32r(aN[i].z);
                As[amIdx[i]][akIdx[i] + 3] = tf32r(aN[i].w);
            }
#pragma unroll
            for (int i = 0; i < 8; i++) {
                int idx = tid + i * 256;
                Bs[idx >> 6][idx & 63] = tf32r(bNv[i]);
            }
            __syncthreads();
        }
    }

    float alv[4][2], arv[4][2];
#pragma unroll
    for (int nf = 0; nf < 4; nf++)
#pragma unroll
        for (int j = 0; j < 2; j++) {
            int col = warpN * 32 + nf * 8 + 2 * tig + j;
            alv[nf][j] = (col < OUTF) ? al2[col] : 0.f;
            arv[nf][j] = (col < OUTF) ? ar2[col] : 0.f;
        }

#pragma unroll
    for (int mf = 0; mf < 2; mf++) {
        int lr0 = warpM * 32 + mf * 16 + g;
        int lr1 = lr0 + 8;
        int r0g = row0 + lr0, r1g = row0 + lr1;
        float el0 = 0.f, er0 = 0.f, el1v = 0.f, er1v = 0.f;
#pragma unroll
        for (int nf = 0; nf < 4; nf++) {
            int colw = warpN * 32 + nf * 8 + 2 * tig;
#pragma unroll
            for (int j = 0; j < 2; j++) {
                int col = colw + j;
                if (col < OUTF) {
                    if (r0g < N) g_feat2[r0g * OUTP + col] = c[mf][nf][j];
                    if (r1g < N) g_feat2[r1g * OUTP + col] = c[mf][nf][2 + j];
                }
            }
            el0 += c[mf][nf][0] * alv[nf][0] + c[mf][nf][1] * alv[nf][1];
            er0 += c[mf][nf][0] * arv[nf][0] + c[mf][nf][1] * arv[nf][1];
            el1v += c[mf][nf][2] * alv[nf][0] + c[mf][nf][3] * alv[nf][1];
            er1v += c[mf][nf][2] * arv[nf][0] + c[mf][nf][3] * arv[nf][1];
        }
#pragma unroll
        for (int o = 1; o < 4; o <<= 1) {
            el0  += __shfl_xor_sync(0xffffffffu, el0,  o, 4);
            er0  += __shfl_xor_sync(0xffffffffu, er0,  o, 4);
            el1v += __shfl_xor_sync(0xffffffffu, el1v, o, 4);
            er1v += __shfl_xor_sync(0xffffffffu, er1v, o, 4);
        }
        if (tig == 0) {
            atomicAdd(&el_sh[lr0], el0);  atomicAdd(&er_sh[lr0], er0);
            atomicAdd(&el_sh[lr1], el1v); atomicAdd(&er_sh[lr1], er1v);
        }
    }
    __syncthreads();
    if (tid < 128) {
        int r = row0 + tid;
        if (r < N) {
            g_el2[r] = el_sh[tid];
            g_er2[r] = er_sh[tid];
        }
    }
}

// ---------------- layer2: softmax + agg + log_softmax (warp per node) -------
__global__ void agg2_ls_kernel(float* __restrict__ out, int N) {
    int warp = threadIdx.x >> 5;
    int lane = threadIdx.x & 31;
    int n = blockIdx.x * 4 + warp;
    if (n >= N) return;
    int r0 = g_rowptr[n];
    int deg = g_rowptr[n + 1] - r0;
    float ern = g_er2[n];

    float mx = -INFINITY;
    for (int i = lane; i < deg; i += 32) {
        int s = g_esrc[r0 + i];
        float x = g_el2[s] + ern;
        x = (x > 0.f) ? x : NEG * x;
        mx = fmaxf(mx, x);
    }
#pragma unroll
    for (int o = 16; o; o >>= 1)
        mx = fmaxf(mx, __shfl_xor_sync(0xffffffffu, mx, o));

    float den = 0.f;
    for (int i = lane; i < deg; i += 32) {
        int s = g_esrc[r0 + i];
        float x = g_el2[s] + ern;
        x = (x > 0.f) ? x : NEG * x;
        den += __expf(x - mx);
    }
#pragma unroll
    for (int o = 16; o; o >>= 1)
        den += __shfl_xor_sync(0xffffffffu, den, o);
    den = fmaxf(den, 1e-9f);

    bool hi = (lane + 32) < OUTF;
    float a0 = 0.f, a1 = 0.f;
    for (int i = 0; i < deg; i++) {
        int s = g_esrc[r0 + i];
        float x = g_el2[s] + ern;
        x = (x > 0.f) ? x : NEG * x;
        float w = __expf(x - mx);
        a0 += w * g_feat2[s * OUTP + lane];
        if (hi) a1 += w * g_feat2[s * OUTP + lane + 32];
    }
    a0 /= den;
    a1 /= den;

    float v0 = a0;
    float v1 = hi ? a1 : -INFINITY;
    float m2 = fmaxf(v0, v1);
#pragma unroll
    for (int o = 16; o; o >>= 1)
        m2 = fmaxf(m2, __shfl_xor_sync(0xffffffffu, m2, o));
    float s_ = expf(v0 - m2) + (hi ? expf(v1 - m2) : 0.f);
#pragma unroll
    for (int o = 16; o; o >>= 1)
        s_ += __shfl_xor_sync(0xffffffffu, s_, o);
    float ls = logf(s_) + m2;
    out[n * OUTF + lane] = v0 - ls;
    if (hi) out[n * OUTF + lane + 32] = v1 - ls;
}

// ---------------- launch ----------------
extern "C" void kernel_launch(void* const* d_in, const int* in_sizes, int n_in,
                              void* d_out, int out_size) {
    const float* features = (const float*)d_in[0];
    const int*   src      = (const int*)d_in[1];
    const int*   dst      = (const int*)d_in[2];
    const float* W1       = (const float*)d_in[3];
    const float* al1      = (const float*)d_in[4];
    const float* ar1      = (const float*)d_in[5];
    const float* W2       = (const float*)d_in[6];
    const float* al2      = (const float*)d_in[7];
    const float* ar2      = (const float*)d_in[8];
    float* out = (float*)d_out;

    int N = in_sizes[0] / IN_F;   // 10000
    int E = in_sizes[1];          // 320000
    if (N > N_NODES) N = N_NODES;
    if (E > N_EDGES) E = N_EDGES;

    int e4blocks = (E / 4 + 255) / 256 + 1;
    count_kernel<<<e4blocks, 256>>>(dst, E);
    scan_kernel<<<1, 1024>>>();

    int gx = (N + 127) / 128;
    gemm1_scatter_kernel<<<gx * NH + e4blocks, 256>>>(
        features, W1, al1, ar1, src, dst, N, E, gx);

    sfm_agg1_kernel<<<(N + 7) / 8, 256>>>(N);
    gemm2_attn_kernel<<<(N + 127) / 128, 256>>>(W2, al2, ar2, N);
    agg2_ls_kernel<<<(N + 3) / 4, 128>>>(out, N);
}